// round 8
// baseline (speedup 1.0000x reference)
#include <cuda_runtime.h>
#include <math.h>

// ---------------- problem constants ----------------
#define N_NODES 50000
#define N_EDGES 600000

// ---------------- scratch (no allocations allowed) ----------------
__device__ float g_B1[(size_t)N_NODES * 128];   // [N,128] buffer
__device__ float g_B2[(size_t)N_NODES * 256];   // [N,256] buffer
__device__ float g_dinv[N_NODES];
__device__ int   g_indptr[N_NODES + 1];
__device__ int   g_cursor[N_NODES];             // counts, then fill cursor
__device__ int   g_srcs[N_EDGES];
__device__ int   g_blocksums[128];

// ================= CSR build =================
__global__ void k_zero(int* cursor) {
    int i = blockIdx.x * blockDim.x + threadIdx.x;
    if (i < N_NODES) cursor[i] = 0;
}

__global__ void k_count(int* cursor, const int* __restrict__ ei) {
    int e = blockIdx.x * blockDim.x + threadIdx.x;
    if (e < N_EDGES) atomicAdd(&cursor[ei[N_EDGES + e]], 1);
}

// per-block inclusive scan of 512 counts -> exclusive indptr (local), dinv
__global__ void k_scan1(const int* __restrict__ counts, int* indptr,
                        int* blocksums, float* dinv) {
    __shared__ int sm[512];
    int i = blockIdx.x * 512 + threadIdx.x;
    int c = (i < N_NODES) ? counts[i] : 0;
    if (i < N_NODES) dinv[i] = rsqrtf((float)(c + 1));  // +1 self loop
    sm[threadIdx.x] = c;
    __syncthreads();
#pragma unroll
    for (int off = 1; off < 512; off <<= 1) {
        int v = (threadIdx.x >= off) ? sm[threadIdx.x - off] : 0;
        __syncthreads();
        sm[threadIdx.x] += v;
        __syncthreads();
    }
    if (i < N_NODES) indptr[i] = sm[threadIdx.x] - c;  // exclusive
    if (threadIdx.x == 511) blocksums[blockIdx.x] = sm[511];
}

__global__ void k_scan2(int* blocksums, int nb) {
    __shared__ int sm[128];
    int t = threadIdx.x;
    int v = (t < nb) ? blocksums[t] : 0;
    sm[t] = v;
    __syncthreads();
#pragma unroll
    for (int off = 1; off < 128; off <<= 1) {
        int u = (t >= off) ? sm[t - off] : 0;
        __syncthreads();
        sm[t] += u;
        __syncthreads();
    }
    if (t < nb) blocksums[t] = sm[t] - v;  // exclusive block offsets
}

__global__ void k_scan3(int* indptr, const int* __restrict__ blocksums, int* cursor) {
    int i = blockIdx.x * blockDim.x + threadIdx.x;
    if (i < N_NODES) {
        indptr[i] += blocksums[i >> 9];
        cursor[i] = 0;
    }
    if (i == 0) indptr[N_NODES] = N_EDGES;
}

__global__ void k_fill(const int* __restrict__ ei, const int* __restrict__ indptr,
                       int* cursor, int* srcs) {
    int e = blockIdx.x * blockDim.x + threadIdx.x;
    if (e >= N_EDGES) return;
    int d = ei[N_EDGES + e];
    int pos = indptr[d] + atomicAdd(&cursor[d], 1);
    srcs[pos] = ei[e];
}

// ================= gather aggregation, 128 channels (R4 unroll-2) =================
__global__ void k_gather128(const float* __restrict__ H, float* __restrict__ OUT,
                            const int* __restrict__ indptr, const int* __restrict__ srcs,
                            const float* __restrict__ dinv,
                            const float* __restrict__ bias, int do_relu) {
    int gt = blockIdx.x * blockDim.x + threadIdx.x;
    int n = gt >> 5;
    int lane = gt & 31;
    if (n >= N_NODES) return;
    const float4* Hv = (const float4*)H;
    float dn = dinv[n];
    float s0 = dn * dn;
    float4 acc = Hv[n * 32 + lane];
    acc.x *= s0; acc.y *= s0; acc.z *= s0; acc.w *= s0;
    int j = indptr[n], end = indptr[n + 1];
    for (; j + 1 < end; j += 2) {
        int s1 = srcs[j], s2 = srcs[j + 1];
        float n1 = dinv[s1] * dn, n2 = dinv[s2] * dn;
        float4 v1 = Hv[s1 * 32 + lane];
        float4 v2 = Hv[s2 * 32 + lane];
        acc.x += v1.x * n1 + v2.x * n2;
        acc.y += v1.y * n1 + v2.y * n2;
        acc.z += v1.z * n1 + v2.z * n2;
        acc.w += v1.w * n1 + v2.w * n2;
    }
    if (j < end) {
        int s1 = srcs[j];
        float n1 = dinv[s1] * dn;
        float4 v1 = Hv[s1 * 32 + lane];
        acc.x += v1.x * n1; acc.y += v1.y * n1;
        acc.z += v1.z * n1; acc.w += v1.w * n1;
    }
    if (bias) {
        float4 b = ((const float4*)bias)[lane];
        acc.x += b.x; acc.y += b.y; acc.z += b.z; acc.w += b.w;
    }
    if (do_relu) {
        acc.x = fmaxf(acc.x, 0.f); acc.y = fmaxf(acc.y, 0.f);
        acc.z = fmaxf(acc.z, 0.f); acc.w = fmaxf(acc.w, 0.f);
    }
    ((float4*)OUT)[n * 32 + lane] = acc;
}

// ================= SGEMM with packed f32x2 FMA, BK=16 =================
// C[M,N] = A[M,K] @ B[K,N] (+bias, relu). BM=BN=128, BK=16, 256 threads, 8x8/thread.
typedef unsigned long long ull;

__device__ __forceinline__ ull pack2(float lo, float hi) {
    ull r;
    asm("mov.b64 %0, {%1, %2};" : "=l"(r) : "r"(__float_as_uint(lo)), "r"(__float_as_uint(hi)));
    return r;
}
__device__ __forceinline__ void unpack2(ull v, float& lo, float& hi) {
    unsigned a, b;
    asm("mov.b64 {%0, %1}, %2;" : "=r"(a), "=r"(b) : "l"(v));
    lo = __uint_as_float(a); hi = __uint_as_float(b);
}
__device__ __forceinline__ void fma2(ull& d, ull a, ull b) {
    asm("fma.rn.f32x2 %0, %1, %2, %0;" : "+l"(d) : "l"(a), "l"(b));
}

__global__ __launch_bounds__(256, 2) void k_sgemm2(const float* __restrict__ A,
                                                   const float* __restrict__ B,
                                                   float* __restrict__ C,
                                                   int M, int K, int N,
                                                   const float* __restrict__ bias,
                                                   int do_relu) {
    __shared__ __align__(16) float As[16][128];  // [k][row]
    __shared__ __align__(16) float Bs[16][128];  // [k][col]

    int tid = threadIdx.x;
    int tx = tid & 15;         // 0..15 col octs
    int ty = tid >> 4;         // 0..15 row octs
    int rowBase = blockIdx.y * 128;
    int colBase = blockIdx.x * 128;

    int arow = tid >> 1;            // 0..127
    int ak   = (tid & 1) * 8;       // 0 or 8
    int brow = tid >> 4;            // 0..15
    int bcol = (tid & 15) * 8;      // 0..120

    ull acc[4][8];                  // [row-pair][col] packed (r2i, r2i+1)
#pragma unroll
    for (int i = 0; i < 4; i++)
#pragma unroll
        for (int j = 0; j < 8; j++) acc[i][j] = 0ull;

    for (int k0 = 0; k0 < K; k0 += 16) {
        int gr = rowBase + arow;
        float4 av0 = make_float4(0.f, 0.f, 0.f, 0.f);
        float4 av1 = make_float4(0.f, 0.f, 0.f, 0.f);
        if (gr < M) {
            av0 = *(const float4*)(A + (size_t)gr * K + k0 + ak);
            av1 = *(const float4*)(A + (size_t)gr * K + k0 + ak + 4);
        }
        As[ak + 0][arow] = av0.x;
        As[ak + 1][arow] = av0.y;
        As[ak + 2][arow] = av0.z;
        As[ak + 3][arow] = av0.w;
        As[ak + 4][arow] = av1.x;
        As[ak + 5][arow] = av1.y;
        As[ak + 6][arow] = av1.z;
        As[ak + 7][arow] = av1.w;

        float4 bv0 = *(const float4*)(B + (size_t)(k0 + brow) * N + colBase + bcol);
        float4 bv1 = *(const float4*)(B + (size_t)(k0 + brow) * N + colBase + bcol + 4);
        *(float4*)&Bs[brow][bcol] = bv0;
        *(float4*)&Bs[brow][bcol + 4] = bv1;
        __syncthreads();

#pragma unroll
        for (int kk = 0; kk < 16; kk++) {
            ulonglong2 a01 = *(const ulonglong2*)&As[kk][ty * 8];       // rows (0,1),(2,3)
            ulonglong2 a23 = *(const ulonglong2*)&As[kk][ty * 8 + 4];   // rows (4,5),(6,7)
            float4 b0 = *(const float4*)&Bs[kk][tx * 8];
            float4 b1 = *(const float4*)&Bs[kk][tx * 8 + 4];
            ull ap[4] = {a01.x, a01.y, a23.x, a23.y};
            ull bd[8];
            bd[0] = pack2(b0.x, b0.x); bd[1] = pack2(b0.y, b0.y);
            bd[2] = pack2(b0.z, b0.z); bd[3] = pack2(b0.w, b0.w);
            bd[4] = pack2(b1.x, b1.x); bd[5] = pack2(b1.y, b1.y);
            bd[6] = pack2(b1.z, b1.z); bd[7] = pack2(b1.w, b1.w);
#pragma unroll
            for (int i = 0; i < 4; i++)
#pragma unroll
                for (int j = 0; j < 8; j++) fma2(acc[i][j], ap[i], bd[j]);
        }
        __syncthreads();
    }

    // epilogue
#pragma unroll
    for (int i = 0; i < 4; i++) {
        float lo[8], hi[8];
#pragma unroll
        for (int j = 0; j < 8; j++) unpack2(acc[i][j], lo[j], hi[j]);
#pragma unroll
        for (int p = 0; p < 2; p++) {
            int row = rowBase + ty * 8 + 2 * i + p;
            if (row >= M) continue;
            float* src = p ? hi : lo;
            float o[8];
#pragma unroll
            for (int j = 0; j < 8; j++) {
                float v = src[j];
                if (bias) v += bias[colBase + tx * 8 + j];
                if (do_relu) v = fmaxf(v, 0.f);
                o[j] = v;
            }
            float* outp = C + (size_t)row * N + colBase + tx * 8;
            *(float4*)(outp) = make_float4(o[0], o[1], o[2], o[3]);
            *(float4*)(outp + 4) = make_float4(o[4], o[5], o[6], o[7]);
        }
    }
}

// ================= layer 3 =================
__global__ void k_gemm_small(const float* __restrict__ H2, const float* __restrict__ W3,
                             float* __restrict__ H3) {
    __shared__ float w[256];
    if (threadIdx.x < 256) w[threadIdx.x] = W3[threadIdx.x];
    __syncthreads();
    int r = blockIdx.x * blockDim.x + threadIdx.x;
    if (r >= N_NODES) return;
    float a0 = 0.f, a1 = 0.f;
    const float4* row = (const float4*)(H2 + (size_t)r * 128);
#pragma unroll
    for (int k = 0; k < 32; k++) {
        float4 v = row[k];
        int b = k * 8;
        a0 += v.x * w[b + 0] + v.y * w[b + 2] + v.z * w[b + 4] + v.w * w[b + 6];
        a1 += v.x * w[b + 1] + v.y * w[b + 3] + v.z * w[b + 5] + v.w * w[b + 7];
    }
    H3[(size_t)r * 2 + 0] = a0;
    H3[(size_t)r * 2 + 1] = a1;
}

// gather 2ch + bias + log_softmax, one thread per node
__global__ void k_gather2_lsm(const float* __restrict__ H3, float* __restrict__ OUT,
                              const int* __restrict__ indptr, const int* __restrict__ srcs,
                              const float* __restrict__ dinv, const float* __restrict__ b3) {
    int n = blockIdx.x * blockDim.x + threadIdx.x;
    if (n >= N_NODES) return;
    float dn = dinv[n];
    float s0 = dn * dn;
    float2 h = *(const float2*)(H3 + (size_t)n * 2);
    float a0 = h.x * s0, a1 = h.y * s0;
    int end = indptr[n + 1];
    for (int j = indptr[n]; j < end; j++) {
        int s = srcs[j];
        float nrm = dinv[s] * dn;
        float2 v = *(const float2*)(H3 + (size_t)s * 2);
        a0 += v.x * nrm;
        a1 += v.y * nrm;
    }
    float v0 = a0 + b3[0];
    float v1 = a1 + b3[1];
    float m = fmaxf(v0, v1);
    float lse = m + logf(expf(v0 - m) + expf(v1 - m));
    OUT[(size_t)n * 2 + 0] = v0 - lse;
    OUT[(size_t)n * 2 + 1] = v1 - lse;
}

// ---------------- launch ----------------
extern "C" void kernel_launch(void* const* d_in, const int* in_sizes, int n_in,
                              void* d_out, int out_size) {
    const float* x  = (const float*)d_in[0];
    const float* W1 = (const float*)d_in[1];
    const float* b1 = (const float*)d_in[2];
    const float* W2 = (const float*)d_in[3];
    const float* b2 = (const float*)d_in[4];
    const float* W3 = (const float*)d_in[5];
    const float* b3 = (const float*)d_in[6];
    const int*   ei = (const int*)d_in[7];   // int32 (JAX x64 disabled)
    float* out = (float*)d_out;

    float *B1, *B2, *dinv;
    int *indptr, *cursor, *srcs, *blocksums;
    cudaGetSymbolAddress((void**)&B1, g_B1);
    cudaGetSymbolAddress((void**)&B2, g_B2);
    cudaGetSymbolAddress((void**)&dinv, g_dinv);
    cudaGetSymbolAddress((void**)&indptr, g_indptr);
    cudaGetSymbolAddress((void**)&cursor, g_cursor);
    cudaGetSymbolAddress((void**)&srcs, g_srcs);
    cudaGetSymbolAddress((void**)&blocksums, g_blocksums);

    const int N = N_NODES, E = N_EDGES, TB = 256;
    const int nScanBlocks = (N + 511) / 512;  // 98

    // ---- CSR build + dinv ----
    k_zero <<<(N + TB - 1) / TB, TB>>>(cursor);
    k_count<<<(E + TB - 1) / TB, TB>>>(cursor, ei);
    k_scan1<<<nScanBlocks, 512>>>(cursor, indptr, blocksums, dinv);
    k_scan2<<<1, 128>>>(blocksums, nScanBlocks);
    k_scan3<<<(N + TB - 1) / TB, TB>>>(indptr, blocksums, cursor);
    k_fill <<<(E + TB - 1) / TB, TB>>>(ei, indptr, cursor, srcs);

    // ---- layer 1: agg(x) -> B1; relu((A x)@W1 + b1) -> B2 ----
    k_gather128<<<(N * 32 + TB - 1) / TB, TB>>>(x, B1, indptr, srcs, dinv, nullptr, 0);
    {
        dim3 g(2, (N + 127) / 128);
        k_sgemm2<<<g, 256>>>(B1, W1, B2, N, 128, 256, b1, 1);
    }

    // ---- layer 2: h1@W2 -> B1; relu(agg + b2) -> B2 ----
    {
        dim3 g(1, (N + 127) / 128);
        k_sgemm2<<<g, 256>>>(B2, W2, B1, N, 256, 128, nullptr, 0);
    }
    k_gather128<<<(N * 32 + TB - 1) / TB, TB>>>(B1, B2, indptr, srcs, dinv, b2, 1);

    // ---- layer 3: h2@W3 -> B1[:, :2]; agg + b3 + log_softmax -> out ----
    k_gemm_small<<<(N + TB - 1) / TB, TB>>>(B2, W3, B1);
    k_gather2_lsm<<<(N + TB - 1) / TB, TB>>>(B1, out, indptr, srcs, dinv, b3);
}

// round 10
// speedup vs baseline: 1.4691x; 1.4691x over previous
#include <cuda_runtime.h>
#include <math.h>

// ---------------- problem constants ----------------
#define N_NODES 50000
#define N_EDGES 600000

// ---------------- scratch (no allocations allowed) ----------------
__device__ float g_B1[(size_t)N_NODES * 128];   // [N,128] buffer
__device__ float g_B2[(size_t)N_NODES * 256];   // [N,256] buffer
__device__ float g_dinv[N_NODES];
__device__ int   g_indptr[N_NODES + 1];
__device__ int   g_cursor[N_NODES];             // counts, then fill cursor
__device__ int   g_srcs[N_EDGES];
__device__ int   g_blocksums[128];

// ================= CSR build =================
__global__ void k_zero(int* cursor) {
    int i = blockIdx.x * blockDim.x + threadIdx.x;
    if (i < N_NODES) cursor[i] = 0;
}

__global__ void k_count(int* cursor, const int* __restrict__ ei) {
    int e = blockIdx.x * blockDim.x + threadIdx.x;
    if (e < N_EDGES) atomicAdd(&cursor[ei[N_EDGES + e]], 1);
}

// per-block inclusive scan of 512 counts -> exclusive indptr (local), dinv
__global__ void k_scan1(const int* __restrict__ counts, int* indptr,
                        int* blocksums, float* dinv) {
    __shared__ int sm[512];
    int i = blockIdx.x * 512 + threadIdx.x;
    int c = (i < N_NODES) ? counts[i] : 0;
    if (i < N_NODES) dinv[i] = rsqrtf((float)(c + 1));  // +1 self loop
    sm[threadIdx.x] = c;
    __syncthreads();
#pragma unroll
    for (int off = 1; off < 512; off <<= 1) {
        int v = (threadIdx.x >= off) ? sm[threadIdx.x - off] : 0;
        __syncthreads();
        sm[threadIdx.x] += v;
        __syncthreads();
    }
    if (i < N_NODES) indptr[i] = sm[threadIdx.x] - c;  // exclusive
    if (threadIdx.x == 511) blocksums[blockIdx.x] = sm[511];
}

// merged (old scan2+scan3): every CTA redundantly prefixes the 98 block sums
// in smem, then applies its offsets, zeroes cursor, sets indptr[N].
__global__ void k_scan23(int* indptr, const int* __restrict__ blocksums,
                         int* cursor, int nb) {
    __shared__ int pre[128];
    if (threadIdx.x < 128) pre[threadIdx.x] = (threadIdx.x < nb) ? blocksums[threadIdx.x] : 0;
    __syncthreads();
    if (threadIdx.x == 0) {
        int run = 0;
        for (int b = 0; b < nb; b++) { int v = pre[b]; pre[b] = run; run += v; }
    }
    __syncthreads();
    int i = blockIdx.x * blockDim.x + threadIdx.x;
    if (i < N_NODES) {
        indptr[i] += pre[i >> 9];
        cursor[i] = 0;
    }
    if (i == 0) indptr[N_NODES] = N_EDGES;
}

__global__ void k_fill(const int* __restrict__ ei, const int* __restrict__ indptr,
                       int* cursor, int* srcs) {
    int e = blockIdx.x * blockDim.x + threadIdx.x;
    if (e >= N_EDGES) return;
    int d = ei[N_EDGES + e];
    int pos = indptr[d] + atomicAdd(&cursor[d], 1);
    srcs[pos] = ei[e];
}

// ================= gather aggregation, 128 channels (R4 unroll-2) =================
__global__ void k_gather128(const float* __restrict__ H, float* __restrict__ OUT,
                            const int* __restrict__ indptr, const int* __restrict__ srcs,
                            const float* __restrict__ dinv,
                            const float* __restrict__ bias, int do_relu) {
    int gt = blockIdx.x * blockDim.x + threadIdx.x;
    int n = gt >> 5;
    int lane = gt & 31;
    if (n >= N_NODES) return;
    const float4* Hv = (const float4*)H;
    float dn = dinv[n];
    float s0 = dn * dn;
    float4 acc = Hv[n * 32 + lane];
    acc.x *= s0; acc.y *= s0; acc.z *= s0; acc.w *= s0;
    int j = indptr[n], end = indptr[n + 1];
    for (; j + 1 < end; j += 2) {
        int s1 = srcs[j], s2 = srcs[j + 1];
        float n1 = dinv[s1] * dn, n2 = dinv[s2] * dn;
        float4 v1 = Hv[s1 * 32 + lane];
        float4 v2 = Hv[s2 * 32 + lane];
        acc.x += v1.x * n1 + v2.x * n2;
        acc.y += v1.y * n1 + v2.y * n2;
        acc.z += v1.z * n1 + v2.z * n2;
        acc.w += v1.w * n1 + v2.w * n2;
    }
    if (j < end) {
        int s1 = srcs[j];
        float n1 = dinv[s1] * dn;
        float4 v1 = Hv[s1 * 32 + lane];
        acc.x += v1.x * n1; acc.y += v1.y * n1;
        acc.z += v1.z * n1; acc.w += v1.w * n1;
    }
    if (bias) {
        float4 b = ((const float4*)bias)[lane];
        acc.x += b.x; acc.y += b.y; acc.z += b.z; acc.w += b.w;
    }
    if (do_relu) {
        acc.x = fmaxf(acc.x, 0.f); acc.y = fmaxf(acc.y, 0.f);
        acc.z = fmaxf(acc.z, 0.f); acc.w = fmaxf(acc.w, 0.f);
    }
    ((float4*)OUT)[n * 32 + lane] = acc;
}

// ================= SGEMM with packed f32x2 FMA (R4 known-good, verbatim) =================
// C[M,N] = A[M,K] @ B[K,N] (+bias, relu). BM=BN=128, BK=8, 256 threads, 8x8/thread.
typedef unsigned long long ull;

__device__ __forceinline__ ull pack2(float lo, float hi) {
    ull r;
    asm("mov.b64 %0, {%1, %2};" : "=l"(r) : "r"(__float_as_uint(lo)), "r"(__float_as_uint(hi)));
    return r;
}
__device__ __forceinline__ void unpack2(ull v, float& lo, float& hi) {
    unsigned a, b;
    asm("mov.b64 {%0, %1}, %2;" : "=r"(a), "=r"(b) : "l"(v));
    lo = __uint_as_float(a); hi = __uint_as_float(b);
}
__device__ __forceinline__ void fma2(ull& d, ull a, ull b) {
    asm("fma.rn.f32x2 %0, %1, %2, %0;" : "+l"(d) : "l"(a), "l"(b));
}

__global__ __launch_bounds__(256) void k_sgemm2(const float* __restrict__ A,
                                                const float* __restrict__ B,
                                                float* __restrict__ C,
                                                int M, int K, int N,
                                                const float* __restrict__ bias,
                                                int do_relu) {
    __shared__ __align__(16) float As[8][128];  // [k][row]
    __shared__ __align__(16) float Bs[8][128];  // [k][col]

    int tid = threadIdx.x;
    int tx = tid & 15;         // 0..15 col octs
    int ty = tid >> 4;         // 0..15 row octs
    int rowBase = blockIdx.y * 128;
    int colBase = blockIdx.x * 128;

    int arow = tid >> 1;            // 0..127
    int ak   = (tid & 1) * 4;       // 0 or 4
    int brow = tid >> 5;            // 0..7
    int bcol = (tid & 31) * 4;      // 0..124

    ull acc[4][8];                  // [row-pair][col] packed (r2i, r2i+1)
#pragma unroll
    for (int i = 0; i < 4; i++)
#pragma unroll
        for (int j = 0; j < 8; j++) acc[i][j] = 0ull;

    for (int k0 = 0; k0 < K; k0 += 8) {
        int gr = rowBase + arow;
        float4 av = make_float4(0.f, 0.f, 0.f, 0.f);
        if (gr < M) av = *(const float4*)(A + (size_t)gr * K + k0 + ak);
        As[ak + 0][arow] = av.x;
        As[ak + 1][arow] = av.y;
        As[ak + 2][arow] = av.z;
        As[ak + 3][arow] = av.w;

        float4 bv = *(const float4*)(B + (size_t)(k0 + brow) * N + colBase + bcol);
        *(float4*)&Bs[brow][bcol] = bv;
        __syncthreads();

#pragma unroll
        for (int kk = 0; kk < 8; kk++) {
            ulonglong2 a01 = *(const ulonglong2*)&As[kk][ty * 8];       // rows (0,1),(2,3)
            ulonglong2 a23 = *(const ulonglong2*)&As[kk][ty * 8 + 4];   // rows (4,5),(6,7)
            float4 b0 = *(const float4*)&Bs[kk][tx * 8];
            float4 b1 = *(const float4*)&Bs[kk][tx * 8 + 4];
            ull ap[4] = {a01.x, a01.y, a23.x, a23.y};
            ull bd[8];
            bd[0] = pack2(b0.x, b0.x); bd[1] = pack2(b0.y, b0.y);
            bd[2] = pack2(b0.z, b0.z); bd[3] = pack2(b0.w, b0.w);
            bd[4] = pack2(b1.x, b1.x); bd[5] = pack2(b1.y, b1.y);
            bd[6] = pack2(b1.z, b1.z); bd[7] = pack2(b1.w, b1.w);
#pragma unroll
            for (int i = 0; i < 4; i++)
#pragma unroll
                for (int j = 0; j < 8; j++) fma2(acc[i][j], ap[i], bd[j]);
        }
        __syncthreads();
    }

    // epilogue
#pragma unroll
    for (int i = 0; i < 4; i++) {
        float lo[8], hi[8];
#pragma unroll
        for (int j = 0; j < 8; j++) unpack2(acc[i][j], lo[j], hi[j]);
#pragma unroll
        for (int p = 0; p < 2; p++) {
            int row = rowBase + ty * 8 + 2 * i + p;
            if (row >= M) continue;
            float* src = p ? hi : lo;
            float o[8];
#pragma unroll
            for (int j = 0; j < 8; j++) {
                float v = src[j];
                if (bias) v += bias[colBase + tx * 8 + j];
                if (do_relu) v = fmaxf(v, 0.f);
                o[j] = v;
            }
            float* outp = C + (size_t)row * N + colBase + tx * 8;
            *(float4*)(outp) = make_float4(o[0], o[1], o[2], o[3]);
            *(float4*)(outp + 4) = make_float4(o[4], o[5], o[6], o[7]);
        }
    }
}

// ================= layer 3 =================
__global__ void k_gemm_small(const float* __restrict__ H2, const float* __restrict__ W3,
                             float* __restrict__ H3) {
    __shared__ float w[256];
    if (threadIdx.x < 256) w[threadIdx.x] = W3[threadIdx.x];
    __syncthreads();
    int r = blockIdx.x * blockDim.x + threadIdx.x;
    if (r >= N_NODES) return;
    float a0 = 0.f, a1 = 0.f;
    const float4* row = (const float4*)(H2 + (size_t)r * 128);
#pragma unroll
    for (int k = 0; k < 32; k++) {
        float4 v = row[k];
        int b = k * 8;
        a0 += v.x * w[b + 0] + v.y * w[b + 2] + v.z * w[b + 4] + v.w * w[b + 6];
        a1 += v.x * w[b + 1] + v.y * w[b + 3] + v.z * w[b + 5] + v.w * w[b + 7];
    }
    H3[(size_t)r * 2 + 0] = a0;
    H3[(size_t)r * 2 + 1] = a1;
}

// gather 2ch + bias + log_softmax, one thread per node
__global__ void k_gather2_lsm(const float* __restrict__ H3, float* __restrict__ OUT,
                              const int* __restrict__ indptr, const int* __restrict__ srcs,
                              const float* __restrict__ dinv, const float* __restrict__ b3) {
    int n = blockIdx.x * blockDim.x + threadIdx.x;
    if (n >= N_NODES) return;
    float dn = dinv[n];
    float s0 = dn * dn;
    float2 h = *(const float2*)(H3 + (size_t)n * 2);
    float a0 = h.x * s0, a1 = h.y * s0;
    int end = indptr[n + 1];
    for (int j = indptr[n]; j < end; j++) {
        int s = srcs[j];
        float nrm = dinv[s] * dn;
        float2 v = *(const float2*)(H3 + (size_t)s * 2);
        a0 += v.x * nrm;
        a1 += v.y * nrm;
    }
    float v0 = a0 + b3[0];
    float v1 = a1 + b3[1];
    float m = fmaxf(v0, v1);
    float lse = m + logf(expf(v0 - m) + expf(v1 - m));
    OUT[(size_t)n * 2 + 0] = v0 - lse;
    OUT[(size_t)n * 2 + 1] = v1 - lse;
}

// ---------------- launch ----------------
extern "C" void kernel_launch(void* const* d_in, const int* in_sizes, int n_in,
                              void* d_out, int out_size) {
    const float* x  = (const float*)d_in[0];
    const float* W1 = (const float*)d_in[1];
    const float* b1 = (const float*)d_in[2];
    const float* W2 = (const float*)d_in[3];
    const float* b2 = (const float*)d_in[4];
    const float* W3 = (const float*)d_in[5];
    const float* b3 = (const float*)d_in[6];
    const int*   ei = (const int*)d_in[7];   // int32 (JAX x64 disabled)
    float* out = (float*)d_out;

    float *B1, *B2, *dinv;
    int *indptr, *cursor, *srcs, *blocksums;
    cudaGetSymbolAddress((void**)&B1, g_B1);
    cudaGetSymbolAddress((void**)&B2, g_B2);
    cudaGetSymbolAddress((void**)&dinv, g_dinv);
    cudaGetSymbolAddress((void**)&indptr, g_indptr);
    cudaGetSymbolAddress((void**)&cursor, g_cursor);
    cudaGetSymbolAddress((void**)&srcs, g_srcs);
    cudaGetSymbolAddress((void**)&blocksums, g_blocksums);

    const int N = N_NODES, E = N_EDGES, TB = 256;
    const int nScanBlocks = (N + 511) / 512;  // 98

    // ---- CSR build + dinv (5 launches) ----
    k_zero  <<<(N + TB - 1) / TB, TB>>>(cursor);
    k_count <<<(E + TB - 1) / TB, TB>>>(cursor, ei);
    k_scan1 <<<nScanBlocks, 512>>>(cursor, indptr, blocksums, dinv);
    k_scan23<<<(N + TB - 1) / TB, TB>>>(indptr, blocksums, cursor, nScanBlocks);
    k_fill  <<<(E + TB - 1) / TB, TB>>>(ei, indptr, cursor, srcs);

    // ---- layer 1: agg(x) -> B1; relu((A x)@W1 + b1) -> B2 ----
    k_gather128<<<(N * 32 + TB - 1) / TB, TB>>>(x, B1, indptr, srcs, dinv, nullptr, 0);
    {
        dim3 g(2, (N + 127) / 128);
        k_sgemm2<<<g, 256>>>(B1, W1, B2, N, 128, 256, b1, 1);
    }

    // ---- layer 2: h1@W2 -> B1; relu(agg + b2) -> B2 ----
    {
        dim3 g(1, (N + 127) / 128);
        k_sgemm2<<<g, 256>>>(B2, W2, B1, N, 256, 128, nullptr, 0);
    }
    k_gather128<<<(N * 32 + TB - 1) / TB, TB>>>(B1, B2, indptr, srcs, dinv, b2, 1);

    // ---- layer 3: h2@W3 -> B1[:, :2]; agg + b3 + log_softmax -> out ----
    k_gemm_small<<<(N + TB - 1) / TB, TB>>>(B2, W3, B1);
    k_gather2_lsm<<<(N + TB - 1) / TB, TB>>>(B1, out, indptr, srcs, dinv, b3);
}

// round 13
// speedup vs baseline: 2.1709x; 1.4777x over previous
#include <cuda_runtime.h>
#include <cuda_bf16.h>
#include <cstdint>
#include <math.h>

// ---------------- problem constants ----------------
#define N_NODES 50000
#define N_EDGES 600000

// ---------------- scratch (no allocations allowed) ----------------
__device__ float g_B1[(size_t)N_NODES * 128];
__device__ float g_B2[(size_t)N_NODES * 256];
__device__ __nv_bfloat16 g_Xhi[(size_t)N_NODES * 128];
__device__ __nv_bfloat16 g_Xlo[(size_t)N_NODES * 128];
__device__ __nv_bfloat16 g_H1hi[(size_t)N_NODES * 256];
__device__ __nv_bfloat16 g_H1lo[(size_t)N_NODES * 256];
__device__ __nv_bfloat16 g_W1Thi[256 * 128], g_W1Tlo[256 * 128];  // [N][K]
__device__ __nv_bfloat16 g_W2Thi[128 * 256], g_W2Tlo[128 * 256];  // [N][K]
__device__ float g_dinv[N_NODES];
__device__ int   g_indptr[N_NODES + 1];
__device__ int   g_cursor[N_NODES];
__device__ int   g_srcs[N_EDGES];
__device__ int   g_blocksums[128];

// ================= helpers =================
__device__ __forceinline__ void split1(float v, __nv_bfloat16& h, __nv_bfloat16& l) {
    h = __float2bfloat16(v);
    l = __float2bfloat16(v - __bfloat162float(h));
}

// ================= CSR build =================
__global__ void k_zero(int* cursor) {
    int i = blockIdx.x * blockDim.x + threadIdx.x;
    if (i < N_NODES) cursor[i] = 0;
}

__global__ void k_count(int* cursor, const int* __restrict__ ei) {
    int e = blockIdx.x * blockDim.x + threadIdx.x;
    if (e < N_EDGES) atomicAdd(&cursor[ei[N_EDGES + e]], 1);
}

__global__ void k_scan1(const int* __restrict__ counts, int* indptr,
                        int* blocksums, float* dinv) {
    __shared__ int sm[512];
    int i = blockIdx.x * 512 + threadIdx.x;
    int c = (i < N_NODES) ? counts[i] : 0;
    if (i < N_NODES) dinv[i] = rsqrtf((float)(c + 1));
    sm[threadIdx.x] = c;
    __syncthreads();
#pragma unroll
    for (int off = 1; off < 512; off <<= 1) {
        int v = (threadIdx.x >= off) ? sm[threadIdx.x - off] : 0;
        __syncthreads();
        sm[threadIdx.x] += v;
        __syncthreads();
    }
    if (i < N_NODES) indptr[i] = sm[threadIdx.x] - c;
    if (threadIdx.x == 511) blocksums[blockIdx.x] = sm[511];
}

__global__ void k_scan23(int* indptr, const int* __restrict__ blocksums,
                         int* cursor, int nb) {
    __shared__ int pre[128];
    if (threadIdx.x < 128) pre[threadIdx.x] = (threadIdx.x < nb) ? blocksums[threadIdx.x] : 0;
    __syncthreads();
    if (threadIdx.x == 0) {
        int run = 0;
        for (int b = 0; b < nb; b++) { int v = pre[b]; pre[b] = run; run += v; }
    }
    __syncthreads();
    int i = blockIdx.x * blockDim.x + threadIdx.x;
    if (i < N_NODES) {
        indptr[i] += pre[i >> 9];
        cursor[i] = 0;
    }
    if (i == 0) indptr[N_NODES] = N_EDGES;
}

__global__ void k_fill(const int* __restrict__ ei, const int* __restrict__ indptr,
                       int* cursor, int* srcs) {
    int e = blockIdx.x * blockDim.x + threadIdx.x;
    if (e >= N_EDGES) return;
    int d = ei[N_EDGES + e];
    int pos = indptr[d] + atomicAdd(&cursor[d], 1);
    srcs[pos] = ei[e];
}

// ================= W transpose + bf16 split: W[K][N] -> WT hi/lo [N][K] =================
__global__ void k_convWT(const float* __restrict__ W, __nv_bfloat16* __restrict__ Thi,
                         __nv_bfloat16* __restrict__ Tlo, int K, int N) {
    int idx = blockIdx.x * blockDim.x + threadIdx.x;
    if (idx >= K * N) return;
    int n = idx / K, k = idx % K;
    __nv_bfloat16 h, l;
    split1(W[(size_t)k * N + n], h, l);
    Thi[idx] = h;
    Tlo[idx] = l;
}

// ================= gather aggregation, 128 channels (R4 unroll-2) =================
// outF: fp32 out (or null). outHi/outLo: bf16 split out (or null).
__global__ void k_gather128(const float* __restrict__ H, float* __restrict__ outF,
                            __nv_bfloat16* __restrict__ outHi, __nv_bfloat16* __restrict__ outLo,
                            const int* __restrict__ indptr, const int* __restrict__ srcs,
                            const float* __restrict__ dinv,
                            const float* __restrict__ bias, int do_relu) {
    int gt = blockIdx.x * blockDim.x + threadIdx.x;
    int n = gt >> 5;
    int lane = gt & 31;
    if (n >= N_NODES) return;
    const float4* Hv = (const float4*)H;
    float dn = dinv[n];
    float s0 = dn * dn;
    float4 acc = Hv[n * 32 + lane];
    acc.x *= s0; acc.y *= s0; acc.z *= s0; acc.w *= s0;
    int j = indptr[n], end = indptr[n + 1];
    for (; j + 1 < end; j += 2) {
        int s1 = srcs[j], s2 = srcs[j + 1];
        float n1 = dinv[s1] * dn, n2 = dinv[s2] * dn;
        float4 v1 = Hv[s1 * 32 + lane];
        float4 v2 = Hv[s2 * 32 + lane];
        acc.x += v1.x * n1 + v2.x * n2;
        acc.y += v1.y * n1 + v2.y * n2;
        acc.z += v1.z * n1 + v2.z * n2;
        acc.w += v1.w * n1 + v2.w * n2;
    }
    if (j < end) {
        int s1 = srcs[j];
        float n1 = dinv[s1] * dn;
        float4 v1 = Hv[s1 * 32 + lane];
        acc.x += v1.x * n1; acc.y += v1.y * n1;
        acc.z += v1.z * n1; acc.w += v1.w * n1;
    }
    if (bias) {
        float4 b = ((const float4*)bias)[lane];
        acc.x += b.x; acc.y += b.y; acc.z += b.z; acc.w += b.w;
    }
    if (do_relu) {
        acc.x = fmaxf(acc.x, 0.f); acc.y = fmaxf(acc.y, 0.f);
        acc.z = fmaxf(acc.z, 0.f); acc.w = fmaxf(acc.w, 0.f);
    }
    if (outF) ((float4*)outF)[n * 32 + lane] = acc;
    if (outHi) {
        __nv_bfloat16 h0, l0, h1, l1, h2, l2, h3, l3;
        split1(acc.x, h0, l0); split1(acc.y, h1, l1);
        split1(acc.z, h2, l2); split1(acc.w, h3, l3);
        __nv_bfloat162* ph = (__nv_bfloat162*)outHi;
        __nv_bfloat162* pl = (__nv_bfloat162*)outLo;
        __nv_bfloat162 va, vb;
        va.x = h0; va.y = h1; vb.x = h2; vb.y = h3;
        ph[n * 64 + lane * 2] = va; ph[n * 64 + lane * 2 + 1] = vb;
        va.x = l0; va.y = l1; vb.x = l2; vb.y = l3;
        pl[n * 64 + lane * 2] = va; pl[n * 64 + lane * 2 + 1] = vb;
    }
}

// ================= bf16-split tensor-core GEMM =================
// C[M,N] = A[M,K] @ B[K,N]; A as (Ahi,Alo)[M][K], B pre-transposed (BThi,BTlo)[N][K].
// 3-term split, fp32 accum. BM=BN=128, BK=32, 256 thr (8 warps, warp tile 32x64).
__device__ __forceinline__ uint32_t s_u32(const void* p) {
    return (uint32_t)__cvta_generic_to_shared(p);
}
__device__ __forceinline__ void ldsm4(uint32_t* d, uint32_t a) {
    asm volatile("ldmatrix.sync.aligned.m8n8.x4.shared.b16 {%0,%1,%2,%3}, [%4];"
                 : "=r"(d[0]), "=r"(d[1]), "=r"(d[2]), "=r"(d[3]) : "r"(a));
}
__device__ __forceinline__ void mma16816(float* c, const uint32_t* a, uint32_t b0, uint32_t b1) {
    asm volatile("mma.sync.aligned.m16n8k16.row.col.f32.bf16.bf16.f32 "
                 "{%0,%1,%2,%3},{%4,%5,%6,%7},{%8,%9},{%0,%1,%2,%3};"
                 : "+f"(c[0]), "+f"(c[1]), "+f"(c[2]), "+f"(c[3])
                 : "r"(a[0]), "r"(a[1]), "r"(a[2]), "r"(a[3]), "r"(b0), "r"(b1));
}

__global__ void k_mma(const __nv_bfloat16* __restrict__ Ahi, const __nv_bfloat16* __restrict__ Alo,
                      const __nv_bfloat16* __restrict__ BThi, const __nv_bfloat16* __restrict__ BTlo,
                      int M, int K, int N,
                      const float* __restrict__ bias, int do_relu,
                      float* __restrict__ Cf,
                      __nv_bfloat16* __restrict__ Chi, __nv_bfloat16* __restrict__ Clo) {
    __shared__ __nv_bfloat16 sAhi[128][40], sAlo[128][40];
    __shared__ __nv_bfloat16 sBhi[128][40], sBlo[128][40];  // [n][k]

    int tid = threadIdx.x;
    int lane = tid & 31;
    int w = tid >> 5;
    int warpM = (w >> 1) * 32;
    int warpN = (w & 1) * 64;
    int rowBase = blockIdx.y * 128;
    int colBase = blockIdx.x * 128;

    // ldmatrix.x4 lane address: matrix lm = lane/8; row = (lm&1)*8 + lane%8; col = (lm>>1)*8
    int lm = lane >> 3;
    int lrow = ((lm & 1) << 3) + (lane & 7);
    int lcol = (lm >> 1) << 3;

    float acc[2][8][4];
#pragma unroll
    for (int i = 0; i < 2; i++)
#pragma unroll
        for (int j = 0; j < 8; j++)
#pragma unroll
            for (int q = 0; q < 4; q++) acc[i][j][q] = 0.f;

    for (int k0 = 0; k0 < K; k0 += 32) {
#pragma unroll
        for (int s = 0; s < 2; s++) {
            int seg = tid + s * 256;        // 0..511
            int r = seg >> 2;               // 0..127
            int c8 = (seg & 3) * 8;         // 0,8,16,24
            int gr = rowBase + r;
            uint4 vh = make_uint4(0u, 0u, 0u, 0u), vl = make_uint4(0u, 0u, 0u, 0u);
            if (gr < M) {
                vh = *(const uint4*)(Ahi + (size_t)gr * K + k0 + c8);
                vl = *(const uint4*)(Alo + (size_t)gr * K + k0 + c8);
            }
            *(uint4*)&sAhi[r][c8] = vh;
            *(uint4*)&sAlo[r][c8] = vl;
            int bn = colBase + r;           // always valid (N multiple of 128)
            *(uint4*)&sBhi[r][c8] = *(const uint4*)(BThi + (size_t)bn * K + k0 + c8);
            *(uint4*)&sBlo[r][c8] = *(const uint4*)(BTlo + (size_t)bn * K + k0 + c8);
        }
        __syncthreads();

#pragma unroll
        for (int kk = 0; kk < 32; kk += 16) {
            uint32_t ah[2][4], al[2][4];
#pragma unroll
            for (int mi = 0; mi < 2; mi++) {
                ldsm4(ah[mi], s_u32(&sAhi[warpM + mi * 16 + lrow][kk + lcol]));
                ldsm4(al[mi], s_u32(&sAlo[warpM + mi * 16 + lrow][kk + lcol]));
            }
#pragma unroll
            for (int ng = 0; ng < 4; ng++) {
                uint32_t bh[4], bl[4];
                ldsm4(bh, s_u32(&sBhi[warpN + ng * 16 + lrow][kk + lcol]));
                ldsm4(bl, s_u32(&sBlo[warpN + ng * 16 + lrow][kk + lcol]));
                // fragment matrices: [0]=n0-7/k0-7  [1]=n8-15/k0-7  [2]=n0-7/k8-15  [3]=n8-15/k8-15
                // n-low half needs (b[0], b[2]); n-high half needs (b[1], b[3]).
#pragma unroll
                for (int mi = 0; mi < 2; mi++) {
                    mma16816(acc[mi][ng * 2 + 0], ah[mi], bh[0], bh[2]);  // hi*hi, n-low
                    mma16816(acc[mi][ng * 2 + 1], ah[mi], bh[1], bh[3]);  // hi*hi, n-high
                    mma16816(acc[mi][ng * 2 + 0], al[mi], bh[0], bh[2]);  // lo*hi
                    mma16816(acc[mi][ng * 2 + 1], al[mi], bh[1], bh[3]);
                    mma16816(acc[mi][ng * 2 + 0], ah[mi], bl[0], bl[2]);  // hi*lo
                    mma16816(acc[mi][ng * 2 + 1], ah[mi], bl[1], bl[3]);
                }
            }
        }
        __syncthreads();
    }

    // epilogue: c0,c1 = (row g, col tg*2,+1); c2,c3 = (row g+8, same cols)
    int g = lane >> 2, tg = lane & 3;
#pragma unroll
    for (int mi = 0; mi < 2; mi++) {
#pragma unroll
        for (int j = 0; j < 8; j++) {
            int row0 = rowBase + warpM + mi * 16 + g;
            int col = colBase + warpN + j * 8 + tg * 2;
            float c0 = acc[mi][j][0], c1 = acc[mi][j][1];
            float c2 = acc[mi][j][2], c3 = acc[mi][j][3];
            if (bias) {
                float b0v = bias[col], b1v = bias[col + 1];
                c0 += b0v; c1 += b1v; c2 += b0v; c3 += b1v;
            }
            if (do_relu) {
                c0 = fmaxf(c0, 0.f); c1 = fmaxf(c1, 0.f);
                c2 = fmaxf(c2, 0.f); c3 = fmaxf(c3, 0.f);
            }
            if (Cf) {
                if (row0 < M) *(float2*)&Cf[(size_t)row0 * N + col] = make_float2(c0, c1);
                if (row0 + 8 < M) *(float2*)&Cf[(size_t)(row0 + 8) * N + col] = make_float2(c2, c3);
            } else {
                __nv_bfloat16 h0, l0, h1, l1;
                if (row0 < M) {
                    split1(c0, h0, l0); split1(c1, h1, l1);
                    __nv_bfloat162 vh, vl;
                    vh.x = h0; vh.y = h1; vl.x = l0; vl.y = l1;
                    *(__nv_bfloat162*)&Chi[(size_t)row0 * N + col] = vh;
                    *(__nv_bfloat162*)&Clo[(size_t)row0 * N + col] = vl;
                }
                if (row0 + 8 < M) {
                    split1(c2, h0, l0); split1(c3, h1, l1);
                    __nv_bfloat162 vh, vl;
                    vh.x = h0; vh.y = h1; vl.x = l0; vl.y = l1;
                    *(__nv_bfloat162*)&Chi[(size_t)(row0 + 8) * N + col] = vh;
                    *(__nv_bfloat162*)&Clo[(size_t)(row0 + 8) * N + col] = vl;
                }
            }
        }
    }
}

// ================= layer 3 =================
__global__ void k_gemm_small(const float* __restrict__ H2, const float* __restrict__ W3,
                             float* __restrict__ H3) {
    __shared__ float w[256];
    if (threadIdx.x < 256) w[threadIdx.x] = W3[threadIdx.x];
    __syncthreads();
    int r = blockIdx.x * blockDim.x + threadIdx.x;
    if (r >= N_NODES) return;
    float a0 = 0.f, a1 = 0.f;
    const float4* row = (const float4*)(H2 + (size_t)r * 128);
#pragma unroll
    for (int k = 0; k < 32; k++) {
        float4 v = row[k];
        int b = k * 8;
        a0 += v.x * w[b + 0] + v.y * w[b + 2] + v.z * w[b + 4] + v.w * w[b + 6];
        a1 += v.x * w[b + 1] + v.y * w[b + 3] + v.z * w[b + 5] + v.w * w[b + 7];
    }
    H3[(size_t)r * 2 + 0] = a0;
    H3[(size_t)r * 2 + 1] = a1;
}

__global__ void k_gather2_lsm(const float* __restrict__ H3, float* __restrict__ OUT,
                              const int* __restrict__ indptr, const int* __restrict__ srcs,
                              const float* __restrict__ dinv, const float* __restrict__ b3) {
    int n = blockIdx.x * blockDim.x + threadIdx.x;
    if (n >= N_NODES) return;
    float dn = dinv[n];
    float s0 = dn * dn;
    float2 h = *(const float2*)(H3 + (size_t)n * 2);
    float a0 = h.x * s0, a1 = h.y * s0;
    int end = indptr[n + 1];
    for (int j = indptr[n]; j < end; j++) {
        int s = srcs[j];
        float nrm = dinv[s] * dn;
        float2 v = *(const float2*)(H3 + (size_t)s * 2);
        a0 += v.x * nrm;
        a1 += v.y * nrm;
    }
    float v0 = a0 + b3[0];
    float v1 = a1 + b3[1];
    float m = fmaxf(v0, v1);
    float lse = m + logf(expf(v0 - m) + expf(v1 - m));
    OUT[(size_t)n * 2 + 0] = v0 - lse;
    OUT[(size_t)n * 2 + 1] = v1 - lse;
}

// ---------------- launch ----------------
extern "C" void kernel_launch(void* const* d_in, const int* in_sizes, int n_in,
                              void* d_out, int out_size) {
    const float* x  = (const float*)d_in[0];
    const float* W1 = (const float*)d_in[1];
    const float* b1 = (const float*)d_in[2];
    const float* W2 = (const float*)d_in[3];
    const float* b2 = (const float*)d_in[4];
    const float* W3 = (const float*)d_in[5];
    const float* b3 = (const float*)d_in[6];
    const int*   ei = (const int*)d_in[7];   // int32 (JAX x64 disabled)
    float* out = (float*)d_out;

    float *B1, *B2, *dinv;
    int *indptr, *cursor, *srcs, *blocksums;
    __nv_bfloat16 *Xhi, *Xlo, *H1hi, *H1lo, *W1Thi, *W1Tlo, *W2Thi, *W2Tlo;
    cudaGetSymbolAddress((void**)&B1, g_B1);
    cudaGetSymbolAddress((void**)&B2, g_B2);
    cudaGetSymbolAddress((void**)&dinv, g_dinv);
    cudaGetSymbolAddress((void**)&indptr, g_indptr);
    cudaGetSymbolAddress((void**)&cursor, g_cursor);
    cudaGetSymbolAddress((void**)&srcs, g_srcs);
    cudaGetSymbolAddress((void**)&blocksums, g_blocksums);
    cudaGetSymbolAddress((void**)&Xhi, g_Xhi);
    cudaGetSymbolAddress((void**)&Xlo, g_Xlo);
    cudaGetSymbolAddress((void**)&H1hi, g_H1hi);
    cudaGetSymbolAddress((void**)&H1lo, g_H1lo);
    cudaGetSymbolAddress((void**)&W1Thi, g_W1Thi);
    cudaGetSymbolAddress((void**)&W1Tlo, g_W1Tlo);
    cudaGetSymbolAddress((void**)&W2Thi, g_W2Thi);
    cudaGetSymbolAddress((void**)&W2Tlo, g_W2Tlo);

    const int N = N_NODES, E = N_EDGES, TB = 256;
    const int nScanBlocks = (N + 511) / 512;  // 98

    // ---- W transpose/split (independent of CSR chain) ----
    k_convWT<<<(128 * 256 + TB - 1) / TB, TB>>>(W1, W1Thi, W1Tlo, 128, 256);
    k_convWT<<<(256 * 128 + TB - 1) / TB, TB>>>(W2, W2Thi, W2Tlo, 256, 128);

    // ---- CSR build + dinv ----
    k_zero  <<<(N + TB - 1) / TB, TB>>>(cursor);
    k_count <<<(E + TB - 1) / TB, TB>>>(cursor, ei);
    k_scan1 <<<nScanBlocks, 512>>>(cursor, indptr, blocksums, dinv);
    k_scan23<<<(N + TB - 1) / TB, TB>>>(indptr, blocksums, cursor, nScanBlocks);
    k_fill  <<<(E + TB - 1) / TB, TB>>>(ei, indptr, cursor, srcs);

    // ---- layer 1: agg(x) -> (Xhi,Xlo); relu((A x)@W1 + b1) -> (H1hi,H1lo) ----
    k_gather128<<<(N * 32 + TB - 1) / TB, TB>>>(x, nullptr, Xhi, Xlo,
                                                indptr, srcs, dinv, nullptr, 0);
    {
        dim3 g(2, (N + 127) / 128);
        k_mma<<<g, 256>>>(Xhi, Xlo, W1Thi, W1Tlo, N, 128, 256, b1, 1,
                          nullptr, H1hi, H1lo);
    }

    // ---- layer 2: h1@W2 -> B1 (fp32); relu(agg + b2) -> B2 ----
    {
        dim3 g(1, (N + 127) / 128);
        k_mma<<<g, 256>>>(H1hi, H1lo, W2Thi, W2Tlo, N, 256, 128, nullptr, 0,
                          B1, nullptr, nullptr);
    }
    k_gather128<<<(N * 32 + TB - 1) / TB, TB>>>(B1, B2, nullptr, nullptr,
                                                indptr, srcs, dinv, b2, 1);

    // ---- layer 3: h2@W3 -> B1[:, :2]; agg + b3 + log_softmax -> out ----
    k_gemm_small<<<(N + TB - 1) / TB, TB>>>(B2, W3, B1);
    k_gather2_lsm<<<(N + TB - 1) / TB, TB>>>(B1, out, indptr, srcs, dinv, b3);
}